// round 8
// baseline (speedup 1.0000x reference)
#include <cuda_runtime.h>
#include <cuda_fp16.h>
#include <cuda_bf16.h>
#include <cstdint>

#define DH      128
#define NNODES  100000
#define NEDGES  1600000
#define NGRAPHS 512
#define NB_SCAN ((NNODES + 1023) / 1024)

// ---------------- scratch (no allocations allowed) ----------------
__device__ float g_mid[(size_t)NNODES * DH];
__device__ float g_h1 [(size_t)NNODES * DH];
__device__ float g_h2 [(size_t)NNODES * DH];
__device__ float g_pool[NGRAPHS * 3 * DH];
__device__ int   g_cnt[NNODES];
__device__ int   g_rowptr[NNODES + 1];
__device__ int   g_cursor[NNODES];
__device__ int   g_col[NEDGES];
__device__ int   g_bsum[NB_SCAN];
// pre-split, pre-swizzled B tiles ([n][k] fp16, chunk-xor swizzled): 6 x 16384 halves
__device__ __half g_bhi[6 * 16384];
__device__ __half g_blo[6 * 16384];

// ---------------- helpers ----------------
__device__ __forceinline__ uint32_t smem_u32(const void* p) {
    uint32_t a;
    asm("{ .reg .u64 t; cvta.to.shared.u64 t, %1; cvt.u32.u64 %0, t; }" : "=r"(a) : "l"(p));
    return a;
}
__device__ __forceinline__ void red_add_v2(float* p, float a, float b) {
    asm volatile("red.global.add.v2.f32 [%0], {%1,%2};"
                 :: "l"(p), "f"(a), "f"(b) : "memory");
}
__device__ __forceinline__ void ldsm_x4(uint32_t* r, uint32_t a) {
    asm volatile("ldmatrix.sync.aligned.m8n8.x4.shared.b16 {%0,%1,%2,%3}, [%4];"
                 : "=r"(r[0]), "=r"(r[1]), "=r"(r[2]), "=r"(r[3]) : "r"(a));
}
__device__ __forceinline__ void ldsm_x2(uint32_t* r, uint32_t a) {
    asm volatile("ldmatrix.sync.aligned.m8n8.x2.shared.b16 {%0,%1}, [%2];"
                 : "=r"(r[0]), "=r"(r[1]) : "r"(a));
}
__device__ __forceinline__ void mma16816(float* c, const uint32_t* a, const uint32_t* b) {
    asm volatile("mma.sync.aligned.m16n8k16.row.col.f32.f16.f16.f32 "
                 "{%0,%1,%2,%3}, {%4,%5,%6,%7}, {%8,%9}, {%0,%1,%2,%3};"
                 : "+f"(c[0]), "+f"(c[1]), "+f"(c[2]), "+f"(c[3])
                 : "r"(a[0]), "r"(a[1]), "r"(a[2]), "r"(a[3]), "r"(b[0]), "r"(b[1]));
}

// smem regions: A chunk (K=64) hi/lo 16KB each, B (K=128) hi/lo 32KB each = 96KB
#define SM_A_HI 0
#define SM_A_LO 16384
#define SM_B_HI 32768
#define SM_B_LO 65536
#define SM_TOT  98304

// ---------------- zero fill ----------------
__global__ void zero_f4(float* __restrict__ p, int n4) {
    int i = blockIdx.x * blockDim.x + threadIdx.x;
    if (i < n4) reinterpret_cast<float4*>(p)[i] = make_float4(0.f, 0.f, 0.f, 0.f);
}
__global__ void zero_i(int* __restrict__ p, int n) {
    int i = blockIdx.x * blockDim.x + threadIdx.x;
    if (i < n) p[i] = 0;
}

// ---------------- CSR build ----------------
__global__ void hist_kernel(const int* __restrict__ dst, int* __restrict__ cnt, int E) {
    int i = blockIdx.x * blockDim.x + threadIdx.x;
    if (i < E) atomicAdd(cnt + __ldg(dst + i), 1);
}

__global__ void scan1_kernel(const int* __restrict__ cnt, int* __restrict__ rowptr,
                             int* __restrict__ bsum, int N) {
    __shared__ int sh[1024];
    int t = threadIdx.x;
    int i = blockIdx.x * 1024 + t;
    int v = (i < N) ? cnt[i] : 0;
    sh[t] = v;
    __syncthreads();
    #pragma unroll
    for (int off = 1; off < 1024; off <<= 1) {
        int u = (t >= off) ? sh[t - off] : 0;
        __syncthreads();
        sh[t] += u;
        __syncthreads();
    }
    if (i < N) rowptr[i] = sh[t] - v;
    if (t == 1023) bsum[blockIdx.x] = sh[t];
}

__global__ void scan2_kernel(int* __restrict__ bsum, int nb) {
    __shared__ int wsum[4];
    int t = threadIdx.x;
    int lane = t & 31, wid = t >> 5;
    int v0 = (t < nb) ? bsum[t] : 0;
    int v = v0;
    #pragma unroll
    for (int o = 1; o < 32; o <<= 1) {
        int u = __shfl_up_sync(0xffffffffu, v, o);
        if (lane >= o) v += u;
    }
    if (lane == 31) wsum[wid] = v;
    __syncthreads();
    if (t < 32) {
        int w = (t < 4) ? wsum[t] : 0;
        #pragma unroll
        for (int o = 1; o < 4; o <<= 1) {
            int u = __shfl_up_sync(0xffffffffu, w, o);
            if (lane >= o) w += u;
        }
        if (t < 4) wsum[t] = w;
    }
    __syncthreads();
    int base = (wid > 0) ? wsum[wid - 1] : 0;
    if (t < nb) bsum[t] = base + v - v0;
}

__global__ void scan3_kernel(int* __restrict__ rowptr, int* __restrict__ cursor,
                             const int* __restrict__ bsum, int N, int E) {
    int i = blockIdx.x * blockDim.x + threadIdx.x;
    if (i < N) {
        int v = rowptr[i] + bsum[i >> 10];
        rowptr[i] = v;
        cursor[i] = v;
    }
    if (i == 0) rowptr[N] = E;
}

__global__ void fill_kernel(const int* __restrict__ src, const int* __restrict__ dst,
                            int* __restrict__ cursor, int* __restrict__ col, int E) {
    int i = blockIdx.x * blockDim.x + threadIdx.x;
    if (i < E) {
        int p = atomicAdd(cursor + __ldg(dst + i), 1);
        col[p] = __ldg(src + i);
    }
}

// ---------------- prep: split W into fp16 hi/lo, transpose to [n][k], swizzle ----
__global__ void prep_b_kernel(const float* __restrict__ w0, const float* __restrict__ w1,
                              const float* __restrict__ w2, const float* __restrict__ w3,
                              const float* __restrict__ w4, const float* __restrict__ w5) {
    int t = blockIdx.x * blockDim.x + threadIdx.x;
    if (t >= 6 * 16384) return;
    int g = t >> 14;
    int e = t & 16383;                 // e = k*128 + n (coalesced W read)
    const float* W = (g == 0) ? w0 : (g == 1) ? w1 : (g == 2) ? w2 :
                     (g == 3) ? w3 : (g == 4) ? w4 : w5;
    float v = __ldg(W + e);
    int n = e & 127, k = e >> 7;
    __half hi = __float2half_rn(v);
    __half lo = __float2half_rn(v - __half2float(hi));
    int idx = (g << 14) + n * 128 + ((((k >> 3)) ^ (n & 7)) << 3) + (k & 7);
    g_bhi[idx] = hi;
    g_blo[idx] = lo;
}

// ---------------- shared mainloop piece: 4 k-steps over one A chunk ------------
__device__ __forceinline__ void chunk_mainloop(uint32_t sb, int ck, int wm, int wn, int lane,
                                               float (&acc)[4][4][4]) {
    const int aRowL = lane & 15;
    const int aSel  = lane >> 4;
    const int sx    = lane & 7;
    const int bRowL = lane & 7;
    const int bSel  = (lane >> 3) & 1;
    #pragma unroll
    for (int ks = 0; ks < 4; ++ks) {
        uint32_t ah[4][4], al[4][4], bh[4][2], bl[4][2];
        #pragma unroll
        for (int mt = 0; mt < 4; ++mt) {
            int row = wm * 64 + mt * 16 + aRowL;
            uint32_t off = (uint32_t)row * 128 + (uint32_t)(((ks * 2 + aSel) ^ sx) << 4);
            ldsm_x4(ah[mt], sb + SM_A_HI + off);
            ldsm_x4(al[mt], sb + SM_A_LO + off);
        }
        int kg = ck * 4 + ks;
        #pragma unroll
        for (int nt = 0; nt < 4; ++nt) {
            int row = wn * 32 + nt * 8 + bRowL;
            uint32_t off = (uint32_t)row * 256 + (uint32_t)(((kg * 2 + bSel) ^ sx) << 4);
            ldsm_x2(bh[nt], sb + SM_B_HI + off);
            ldsm_x2(bl[nt], sb + SM_B_LO + off);
        }
        #pragma unroll
        for (int mt = 0; mt < 4; ++mt)
            #pragma unroll
            for (int nt = 0; nt < 4; ++nt) {
                mma16816(acc[mt][nt], ah[mt], bh[nt]);
                mma16816(acc[mt][nt], al[mt], bh[nt]);
                mma16816(acc[mt][nt], ah[mt], bl[nt]);
            }
    }
}

// ---------------- B copy piece ----------------
__device__ __forceinline__ void copy_b(char* smem, int tid,
                                       const __half* bhi, const __half* blo) {
    const float4* gh = reinterpret_cast<const float4*>(bhi);
    const float4* gl = reinterpret_cast<const float4*>(blo);
    float4* sh = reinterpret_cast<float4*>(smem + SM_B_HI);
    float4* sl = reinterpret_cast<float4*>(smem + SM_B_LO);
    #pragma unroll
    for (int i = 0; i < 8; ++i) {
        sh[tid + i * 256] = gh[tid + i * 256];
        sl[tid + i * 256] = gl[tid + i * 256];
    }
}

// ---------------- fused gather + GEMM1 (+bias+BN+ReLU) -> mid ----------------
// A chunk ck is gathered (x[i] + sum neighbors, cols [64ck,64ck+64)) directly
// into smem as fp16 hi/lo. Same smem budget as gemm_mma -> 2 CTAs/SM.
__global__ __launch_bounds__(256, 2)
void gather_gemm1(const float* __restrict__ X,
                  const int* __restrict__ rowptr, const int* __restrict__ col,
                  const __half* __restrict__ bhi, const __half* __restrict__ blo,
                  const float* __restrict__ bias,
                  const float* __restrict__ gamma, const float* __restrict__ beta,
                  float* __restrict__ out, int M) {
    extern __shared__ __align__(16) char smem[];
    const uint32_t sb = smem_u32(smem);
    const int tid  = threadIdx.x;
    const int wid  = tid >> 5;
    const int lane = tid & 31;
    const int wm   = wid >> 2;
    const int wn   = wid & 3;
    const int rowBase = blockIdx.x * 128;

    copy_b(smem, tid, bhi, blo);

    float acc[4][4][4];
    #pragma unroll
    for (int i = 0; i < 4; ++i)
        #pragma unroll
        for (int j = 0; j < 4; ++j)
            #pragma unroll
            for (int r = 0; r < 4; ++r) acc[i][j][r] = 0.f;

    #pragma unroll
    for (int ck = 0; ck < 2; ++ck) {
        if (ck == 1) __syncthreads();      // mainloop ck0 done reading A
        // ---- gather chunk ck: each warp 16 rows, lane owns 2 cols (float2) ----
        {
            __half* ah = reinterpret_cast<__half*>(smem + SM_A_HI);
            __half* al = reinterpret_cast<__half*>(smem + SM_A_LO);
            const float2* Xv = reinterpret_cast<const float2*>(X);  // row = 64 float2
            const int colBase = ck * 32 + lane;
            for (int i = 0; i < 16; ++i) {
                int r  = wid * 16 + i;
                int gr = rowBase + r;
                float2 a = make_float2(0.f, 0.f);
                if (gr < M) {
                    a = Xv[(size_t)gr * 64 + colBase];
                    int e   = __ldg(rowptr + gr);
                    int end = __ldg(rowptr + gr + 1);
                    for (; e + 8 <= end; e += 8) {
                        int s0 = __ldg(col + e + 0), s1 = __ldg(col + e + 1);
                        int s2 = __ldg(col + e + 2), s3 = __ldg(col + e + 3);
                        int s4 = __ldg(col + e + 4), s5 = __ldg(col + e + 5);
                        int s6 = __ldg(col + e + 6), s7 = __ldg(col + e + 7);
                        float2 v0 = Xv[(size_t)s0 * 64 + colBase];
                        float2 v1 = Xv[(size_t)s1 * 64 + colBase];
                        float2 v2 = Xv[(size_t)s2 * 64 + colBase];
                        float2 v3 = Xv[(size_t)s3 * 64 + colBase];
                        float2 v4 = Xv[(size_t)s4 * 64 + colBase];
                        float2 v5 = Xv[(size_t)s5 * 64 + colBase];
                        float2 v6 = Xv[(size_t)s6 * 64 + colBase];
                        float2 v7 = Xv[(size_t)s7 * 64 + colBase];
                        a.x += ((v0.x + v1.x) + (v2.x + v3.x)) + ((v4.x + v5.x) + (v6.x + v7.x));
                        a.y += ((v0.y + v1.y) + (v2.y + v3.y)) + ((v4.y + v5.y) + (v6.y + v7.y));
                    }
                    for (; e < end; ++e) {
                        int s = __ldg(col + e);
                        float2 v = Xv[(size_t)s * 64 + colBase];
                        a.x += v.x; a.y += v.y;
                    }
                }
                __half h0 = __float2half_rn(a.x), h1 = __float2half_rn(a.y);
                __half l0 = __float2half_rn(a.x - __half2float(h0));
                __half l1 = __float2half_rn(a.y - __half2float(h1));
                int c0  = lane * 2;                       // 0..62 within chunk
                int idx = r * 64 + (((c0 >> 3) ^ (r & 7)) << 3) + (c0 & 7);
                *reinterpret_cast<__half2*>(ah + idx) = __halves2half2(h0, h1);
                *reinterpret_cast<__half2*>(al + idx) = __halves2half2(l0, l1);
            }
        }
        __syncthreads();
        chunk_mainloop(sb, ck, wm, wn, lane, acc);
    }

    // ---- epilogue: bias + BN + ReLU -> mid ----
    const int g8  = lane >> 2;
    const int tig = lane & 3;
    #pragma unroll
    for (int nt = 0; nt < 4; ++nt) {
        int c0 = wn * 32 + nt * 8 + 2 * tig;
        float cb0 = __ldg(bias + c0),      cb1 = __ldg(bias + c0 + 1);
        float cs0 = __ldg(gamma + c0)     * 0.9999950000374997f;
        float cs1 = __ldg(gamma + c0 + 1) * 0.9999950000374997f;
        float ct0 = __ldg(beta + c0),      ct1 = __ldg(beta + c0 + 1);
        #pragma unroll
        for (int mt = 0; mt < 4; ++mt) {
            #pragma unroll
            for (int hf = 0; hf < 2; ++hf) {
                int row = rowBase + wm * 64 + mt * 16 + g8 + hf * 8;
                if (row < M) {
                    float v0 = fmaxf((acc[mt][nt][2 * hf + 0] + cb0) * cs0 + ct0, 0.f);
                    float v1 = fmaxf((acc[mt][nt][2 * hf + 1] + cb1) * cs1 + ct1, 0.f);
                    *reinterpret_cast<float2*>(out + (size_t)row * DH + c0) =
                        make_float2(v0, v1);
                }
            }
        }
    }
}

// ---------------- GEMM2 (+bias+ReLU+pool, optional hout store) ----------------
template<bool DO_OUT>
__global__ __launch_bounds__(256, 2)
void gemm2_mma(const float* __restrict__ A,
               const __half* __restrict__ bhi, const __half* __restrict__ blo,
               const float* __restrict__ bias,
               float* __restrict__ out,
               const int* __restrict__ batch, int poolOff, int M) {
    extern __shared__ __align__(16) char smem[];
    const uint32_t sb = smem_u32(smem);
    const int tid  = threadIdx.x;
    const int wid  = tid >> 5;
    const int lane = tid & 31;
    const int wm   = wid >> 2;
    const int wn   = wid & 3;
    const int rowBase = blockIdx.x * 128;

    copy_b(smem, tid, bhi, blo);

    float acc[4][4][4];
    #pragma unroll
    for (int i = 0; i < 4; ++i)
        #pragma unroll
        for (int j = 0; j < 4; ++j)
            #pragma unroll
            for (int r = 0; r < 4; ++r) acc[i][j][r] = 0.f;

    #pragma unroll
    for (int ck = 0; ck < 2; ++ck) {
        if (ck == 1) __syncthreads();
        {
            __half* ah = reinterpret_cast<__half*>(smem + SM_A_HI);
            __half* al = reinterpret_cast<__half*>(smem + SM_A_LO);
            #pragma unroll
            for (int it = 0; it < 8; ++it) {
                int gidx = it * 256 + tid;       // 2048 float4
                int row  = gidx >> 4;
                int colI = (gidx & 15) << 2;     // 0..60
                float4 v = make_float4(0.f, 0.f, 0.f, 0.f);
                if (rowBase + row < M)
                    v = *reinterpret_cast<const float4*>(
                        A + (size_t)(rowBase + row) * DH + ck * 64 + colI);
                __half h0 = __float2half_rn(v.x), h1 = __float2half_rn(v.y);
                __half h2 = __float2half_rn(v.z), h3 = __float2half_rn(v.w);
                __half l0 = __float2half_rn(v.x - __half2float(h0));
                __half l1 = __float2half_rn(v.y - __half2float(h1));
                __half l2 = __float2half_rn(v.z - __half2float(h2));
                __half l3 = __float2half_rn(v.w - __half2float(h3));
                int idx = row * 64 + (((colI >> 3) ^ (row & 7)) << 3) + (colI & 7);
                __half2* ph = reinterpret_cast<__half2*>(ah + idx);
                __half2* pl = reinterpret_cast<__half2*>(al + idx);
                ph[0] = __halves2half2(h0, h1); ph[1] = __halves2half2(h2, h3);
                pl[0] = __halves2half2(l0, l1); pl[1] = __halves2half2(l2, l3);
            }
        }
        __syncthreads();
        chunk_mainloop(sb, ck, wm, wn, lane, acc);
    }

    const int g8  = lane >> 2;
    const int tig = lane & 3;
    #pragma unroll
    for (int mt = 0; mt < 4; ++mt) {
        #pragma unroll
        for (int hf = 0; hf < 2; ++hf) {
            int row = rowBase + wm * 64 + mt * 16 + g8 + hf * 8;
            if (row < M) {
                int gI = __ldg(batch + row);
                #pragma unroll
                for (int nt = 0; nt < 4; ++nt) {
                    int c0 = wn * 32 + nt * 8 + 2 * tig;
                    float v0 = fmaxf(acc[mt][nt][2 * hf + 0] + __ldg(bias + c0), 0.f);
                    float v1 = fmaxf(acc[mt][nt][2 * hf + 1] + __ldg(bias + c0 + 1), 0.f);
                    if (DO_OUT)
                        *reinterpret_cast<float2*>(out + (size_t)row * DH + c0) =
                            make_float2(v0, v1);
                    red_add_v2(g_pool + (size_t)gI * (3 * DH) + poolOff + c0, v0, v1);
                }
            }
        }
    }
}

// ---------------- final MLP ----------------
__global__ void final_kernel(const float* __restrict__ pool,
                             const float* __restrict__ w1, const float* __restrict__ b1,
                             const float* __restrict__ w2, const float* __restrict__ b2,
                             float* __restrict__ out) {
    int g = blockIdx.x;
    int tid = threadIdx.x;
    __shared__ float p[384];
    __shared__ float h[384];
    p[tid] = pool[(size_t)g * 384 + tid];
    __syncthreads();
    float acc = b1[tid];
    #pragma unroll 4
    for (int k = 0; k < 384; ++k) acc += p[k] * w1[(size_t)k * 384 + tid];
    h[tid] = fmaxf(acc, 0.f);
    __syncthreads();
    if (tid < 320) {
        int j = tid >> 5, lane = tid & 31;
        float s = 0.f;
        for (int k = lane; k < 384; k += 32) s += h[k] * w2[(size_t)k * 10 + j];
        #pragma unroll
        for (int o = 16; o > 0; o >>= 1) s += __shfl_down_sync(0xffffffffu, s, o);
        if (lane == 0) out[g * 10 + j] = s + b2[j];
    }
}

// ---------------- launch ----------------
extern "C" void kernel_launch(void* const* d_in, const int* in_sizes, int n_in,
                              void* d_out, int out_size) {
    const float* x     = (const float*)d_in[0];
    const int*   ei    = (const int*)d_in[1];
    const int*   batch = (const int*)d_in[2];
    const int E   = in_sizes[1] / 2;
    const int M   = in_sizes[0] / DH;
    const int* src = ei;
    const int* dst = ei + E;

    float *mid, *h1, *h2, *pool;
    __half *bhi, *blo;
    int *cnt, *rowptr, *cursor, *col, *bsum;
    cudaGetSymbolAddress((void**)&mid,    g_mid);
    cudaGetSymbolAddress((void**)&h1,     g_h1);
    cudaGetSymbolAddress((void**)&h2,     g_h2);
    cudaGetSymbolAddress((void**)&pool,   g_pool);
    cudaGetSymbolAddress((void**)&bhi,    g_bhi);
    cudaGetSymbolAddress((void**)&blo,    g_blo);
    cudaGetSymbolAddress((void**)&cnt,    g_cnt);
    cudaGetSymbolAddress((void**)&rowptr, g_rowptr);
    cudaGetSymbolAddress((void**)&cursor, g_cursor);
    cudaGetSymbolAddress((void**)&col,    g_col);
    cudaGetSymbolAddress((void**)&bsum,   g_bsum);

    cudaFuncSetAttribute(gather_gemm1,     cudaFuncAttributeMaxDynamicSharedMemorySize, SM_TOT);
    cudaFuncSetAttribute(gemm2_mma<true>,  cudaFuncAttributeMaxDynamicSharedMemorySize, SM_TOT);
    cudaFuncSetAttribute(gemm2_mma<false>, cudaFuncAttributeMaxDynamicSharedMemorySize, SM_TOT);

    // ---- CSR build ----
    zero_i<<<(M + 255) / 256, 256>>>(cnt, M);
    hist_kernel<<<(E + 255) / 256, 256>>>(dst, cnt, E);
    scan1_kernel<<<NB_SCAN, 1024>>>(cnt, rowptr, bsum, M);
    scan2_kernel<<<1, 128>>>(bsum, NB_SCAN);
    scan3_kernel<<<(M + 255) / 256, 256>>>(rowptr, cursor, bsum, M, E);
    fill_kernel<<<(E + 255) / 256, 256>>>(src, dst, cursor, col, E);

    // ---- prep weights (split + transpose + swizzle) ----
    prep_b_kernel<<<(6 * 16384 + 255) / 256, 256>>>(
        (const float*)d_in[3],  (const float*)d_in[7],
        (const float*)d_in[9],  (const float*)d_in[13],
        (const float*)d_in[15], (const float*)d_in[19]);

    // ---- zero pool accumulator ----
    {
        int n4 = NGRAPHS * 3 * DH / 4;
        zero_f4<<<(n4 + 255) / 256, 256>>>(pool, n4);
    }

    const float* xin = x;
    float* houts[3] = {h1, h2, nullptr};
    const int gblocks = (M + 127) / 128;

    for (int l = 0; l < 3; ++l) {
        const float* bias1 = (const float*)d_in[3 + 6 * l + 1];
        const float* gamma = (const float*)d_in[3 + 6 * l + 2];
        const float* beta  = (const float*)d_in[3 + 6 * l + 3];
        const float* bias2 = (const float*)d_in[3 + 6 * l + 5];
        const __half* bh1 = bhi + (size_t)(2 * l + 0) * 16384;
        const __half* bl1 = blo + (size_t)(2 * l + 0) * 16384;
        const __half* bh2 = bhi + (size_t)(2 * l + 1) * 16384;
        const __half* bl2 = blo + (size_t)(2 * l + 1) * 16384;

        gather_gemm1<<<gblocks, 256, SM_TOT>>>(
            xin, rowptr, col, bh1, bl1, bias1, gamma, beta, mid, M);
        if (l < 2)
            gemm2_mma<true><<<gblocks, 256, SM_TOT>>>(
                mid, bh2, bl2, bias2, houts[l], batch, l * DH, M);
        else
            gemm2_mma<false><<<gblocks, 256, SM_TOT>>>(
                mid, bh2, bl2, bias2, nullptr, batch, l * DH, M);
        xin = houts[l];
    }

    final_kernel<<<NGRAPHS, 384>>>(pool,
                                   (const float*)d_in[21], (const float*)d_in[22],
                                   (const float*)d_in[23], (const float*)d_in[24],
                                   (float*)d_out);
}

// round 9
// speedup vs baseline: 1.6548x; 1.6548x over previous
#include <cuda_runtime.h>
#include <cuda_fp16.h>
#include <cuda_bf16.h>
#include <cstdint>

#define DH      128
#define NNODES  100000
#define NEDGES  1600000
#define NGRAPHS 512
#define NB_SCAN ((NNODES + 1023) / 1024)

// ---------------- scratch (no allocations allowed) ----------------
__device__ float  g_agg[(size_t)NNODES * DH];
__device__ float  g_mid[(size_t)NNODES * DH];
__device__ __half g_xh [(size_t)NNODES * DH];   // fp16 copy of x
__device__ __half g_hh [(size_t)NNODES * DH];   // fp16 h (reused across layers)
__device__ float  g_pool[NGRAPHS * 3 * DH];
__device__ int    g_cnt[NNODES];
__device__ int    g_rowptr[NNODES + 1];
__device__ int    g_cursor[NNODES];
__device__ int    g_col[NEDGES];
__device__ int    g_bsum[NB_SCAN];
// pre-split, pre-swizzled B tiles ([n][k] fp16, chunk-xor swizzled): 6 x 16384 halves
__device__ __half g_bhi[6 * 16384];
__device__ __half g_blo[6 * 16384];

// ---------------- helpers ----------------
__device__ __forceinline__ uint32_t smem_u32(const void* p) {
    uint32_t a;
    asm("{ .reg .u64 t; cvta.to.shared.u64 t, %1; cvt.u32.u64 %0, t; }" : "=r"(a) : "l"(p));
    return a;
}
__device__ __forceinline__ void red_add_v2(float* p, float a, float b) {
    asm volatile("red.global.add.v2.f32 [%0], {%1,%2};"
                 :: "l"(p), "f"(a), "f"(b) : "memory");
}
__device__ __forceinline__ void ldsm_x4(uint32_t* r, uint32_t a) {
    asm volatile("ldmatrix.sync.aligned.m8n8.x4.shared.b16 {%0,%1,%2,%3}, [%4];"
                 : "=r"(r[0]), "=r"(r[1]), "=r"(r[2]), "=r"(r[3]) : "r"(a));
}
__device__ __forceinline__ void ldsm_x2(uint32_t* r, uint32_t a) {
    asm volatile("ldmatrix.sync.aligned.m8n8.x2.shared.b16 {%0,%1}, [%2];"
                 : "=r"(r[0]), "=r"(r[1]) : "r"(a));
}
__device__ __forceinline__ void mma16816(float* c, const uint32_t* a, const uint32_t* b) {
    asm volatile("mma.sync.aligned.m16n8k16.row.col.f32.f16.f16.f32 "
                 "{%0,%1,%2,%3}, {%4,%5,%6,%7}, {%8,%9}, {%0,%1,%2,%3};"
                 : "+f"(c[0]), "+f"(c[1]), "+f"(c[2]), "+f"(c[3])
                 : "r"(a[0]), "r"(a[1]), "r"(a[2]), "r"(a[3]), "r"(b[0]), "r"(b[1]));
}
__device__ __forceinline__ float4 h4_to_f4(uint2 u) {
    __half2 h0 = *reinterpret_cast<__half2*>(&u.x);
    __half2 h1 = *reinterpret_cast<__half2*>(&u.y);
    float2 f0 = __half22float2(h0);
    float2 f1 = __half22float2(h1);
    return make_float4(f0.x, f0.y, f1.x, f1.y);
}

// smem regions: A chunk (K=64) hi/lo 16KB each, B (K=128) hi/lo 32KB each = 96KB
#define SM_A_HI 0
#define SM_A_LO 16384
#define SM_B_HI 32768
#define SM_B_LO 65536
#define SM_TOT  98304

// ---------------- zero / convert ----------------
__global__ void zero_f4(float* __restrict__ p, int n4) {
    int i = blockIdx.x * blockDim.x + threadIdx.x;
    if (i < n4) reinterpret_cast<float4*>(p)[i] = make_float4(0.f, 0.f, 0.f, 0.f);
}
__global__ void zero_i(int* __restrict__ p, int n) {
    int i = blockIdx.x * blockDim.x + threadIdx.x;
    if (i < n) p[i] = 0;
}
__global__ void prep_x_kernel(const float* __restrict__ x, __half* __restrict__ xh, int n2) {
    int i = blockIdx.x * blockDim.x + threadIdx.x;
    if (i < n2) {
        float2 v = reinterpret_cast<const float2*>(x)[i];
        reinterpret_cast<__half2*>(xh)[i] = __float22half2_rn(v);
    }
}

// ---------------- CSR build ----------------
__global__ void hist_kernel(const int* __restrict__ dst, int* __restrict__ cnt, int E) {
    int i = blockIdx.x * blockDim.x + threadIdx.x;
    if (i < E) atomicAdd(cnt + __ldg(dst + i), 1);
}

__global__ void scan1_kernel(const int* __restrict__ cnt, int* __restrict__ rowptr,
                             int* __restrict__ bsum, int N) {
    __shared__ int sh[1024];
    int t = threadIdx.x;
    int i = blockIdx.x * 1024 + t;
    int v = (i < N) ? cnt[i] : 0;
    sh[t] = v;
    __syncthreads();
    #pragma unroll
    for (int off = 1; off < 1024; off <<= 1) {
        int u = (t >= off) ? sh[t - off] : 0;
        __syncthreads();
        sh[t] += u;
        __syncthreads();
    }
    if (i < N) rowptr[i] = sh[t] - v;
    if (t == 1023) bsum[blockIdx.x] = sh[t];
}

__global__ void scan2_kernel(int* __restrict__ bsum, int nb) {
    __shared__ int wsum[4];
    int t = threadIdx.x;
    int lane = t & 31, wid = t >> 5;
    int v0 = (t < nb) ? bsum[t] : 0;
    int v = v0;
    #pragma unroll
    for (int o = 1; o < 32; o <<= 1) {
        int u = __shfl_up_sync(0xffffffffu, v, o);
        if (lane >= o) v += u;
    }
    if (lane == 31) wsum[wid] = v;
    __syncthreads();
    if (t < 32) {
        int w = (t < 4) ? wsum[t] : 0;
        #pragma unroll
        for (int o = 1; o < 4; o <<= 1) {
            int u = __shfl_up_sync(0xffffffffu, w, o);
            if (lane >= o) w += u;
        }
        if (t < 4) wsum[t] = w;
    }
    __syncthreads();
    int base = (wid > 0) ? wsum[wid - 1] : 0;
    if (t < nb) bsum[t] = base + v - v0;
}

__global__ void scan3_kernel(int* __restrict__ rowptr, int* __restrict__ cursor,
                             const int* __restrict__ bsum, int N, int E) {
    int i = blockIdx.x * blockDim.x + threadIdx.x;
    if (i < N) {
        int v = rowptr[i] + bsum[i >> 10];
        rowptr[i] = v;
        cursor[i] = v;
    }
    if (i == 0) rowptr[N] = E;
}

__global__ void fill_kernel(const int* __restrict__ src, const int* __restrict__ dst,
                            int* __restrict__ cursor, int* __restrict__ col, int E) {
    int i = blockIdx.x * blockDim.x + threadIdx.x;
    if (i < E) {
        int p = atomicAdd(cursor + __ldg(dst + i), 1);
        col[p] = __ldg(src + i);
    }
}

// ---------------- gather (fp16 source): agg[i] = x[i] + sum_{j} x[j] ----------
// one warp per node; lane owns 4 halves (8B) of the 256B row
__global__ void gather_f16(const __half* __restrict__ x,
                           const int* __restrict__ rowptr,
                           const int* __restrict__ col,
                           float* __restrict__ agg, int N) {
    int w = (blockIdx.x * blockDim.x + threadIdx.x) >> 5;
    if (w >= N) return;
    int lane = threadIdx.x & 31;
    const uint2* xb = reinterpret_cast<const uint2*>(x);   // row = 32 uint2
    float4 acc = h4_to_f4(xb[(size_t)w * 32 + lane]);      // self term
    int e   = __ldg(rowptr + w);
    int end = __ldg(rowptr + w + 1);
    for (; e + 4 <= end; e += 4) {
        int s0 = __ldg(col + e + 0);
        int s1 = __ldg(col + e + 1);
        int s2 = __ldg(col + e + 2);
        int s3 = __ldg(col + e + 3);
        float4 v0 = h4_to_f4(xb[(size_t)s0 * 32 + lane]);
        float4 v1 = h4_to_f4(xb[(size_t)s1 * 32 + lane]);
        float4 v2 = h4_to_f4(xb[(size_t)s2 * 32 + lane]);
        float4 v3 = h4_to_f4(xb[(size_t)s3 * 32 + lane]);
        acc.x += (v0.x + v1.x) + (v2.x + v3.x);
        acc.y += (v0.y + v1.y) + (v2.y + v3.y);
        acc.z += (v0.z + v1.z) + (v2.z + v3.z);
        acc.w += (v0.w + v1.w) + (v2.w + v3.w);
    }
    for (; e < end; ++e) {
        int s = __ldg(col + e);
        float4 v = h4_to_f4(xb[(size_t)s * 32 + lane]);
        acc.x += v.x; acc.y += v.y; acc.z += v.z; acc.w += v.w;
    }
    reinterpret_cast<float4*>(agg)[(size_t)w * 32 + lane] = acc;
}

// ---------------- prep: split W into fp16 hi/lo, transpose to [n][k], swizzle ----
__global__ void prep_b_kernel(const float* __restrict__ w0, const float* __restrict__ w1,
                              const float* __restrict__ w2, const float* __restrict__ w3,
                              const float* __restrict__ w4, const float* __restrict__ w5) {
    int t = blockIdx.x * blockDim.x + threadIdx.x;
    if (t >= 6 * 16384) return;
    int g = t >> 14;
    int e = t & 16383;                 // e = k*128 + n (coalesced W read)
    const float* W = (g == 0) ? w0 : (g == 1) ? w1 : (g == 2) ? w2 :
                     (g == 3) ? w3 : (g == 4) ? w4 : w5;
    float v = __ldg(W + e);
    int n = e & 127, k = e >> 7;
    __half hi = __float2half_rn(v);
    __half lo = __float2half_rn(v - __half2float(hi));
    int idx = (g << 14) + n * 128 + ((((k >> 3)) ^ (n & 7)) << 3) + (k & 7);
    g_bhi[idx] = hi;
    g_blo[idx] = lo;
}

// ---------------- shared pieces ----------------
__device__ __forceinline__ void copy_b(char* smem, int tid,
                                       const __half* bhi, const __half* blo) {
    const float4* gh = reinterpret_cast<const float4*>(bhi);
    const float4* gl = reinterpret_cast<const float4*>(blo);
    float4* sh = reinterpret_cast<float4*>(smem + SM_B_HI);
    float4* sl = reinterpret_cast<float4*>(smem + SM_B_LO);
    #pragma unroll
    for (int i = 0; i < 8; ++i) {
        sh[tid + i * 256] = gh[tid + i * 256];
        sl[tid + i * 256] = gl[tid + i * 256];
    }
}

__device__ __forceinline__ void load_a_chunk(char* smem, int tid, const float* A,
                                             int rowBase, int ck, int M) {
    __half* ah = reinterpret_cast<__half*>(smem + SM_A_HI);
    __half* al = reinterpret_cast<__half*>(smem + SM_A_LO);
    #pragma unroll
    for (int it = 0; it < 8; ++it) {
        int gidx = it * 256 + tid;       // 2048 float4
        int row  = gidx >> 4;
        int colI = (gidx & 15) << 2;     // 0..60
        float4 v = make_float4(0.f, 0.f, 0.f, 0.f);
        if (rowBase + row < M)
            v = *reinterpret_cast<const float4*>(
                A + (size_t)(rowBase + row) * DH + ck * 64 + colI);
        __half h0 = __float2half_rn(v.x), h1 = __float2half_rn(v.y);
        __half h2 = __float2half_rn(v.z), h3 = __float2half_rn(v.w);
        __half l0 = __float2half_rn(v.x - __half2float(h0));
        __half l1 = __float2half_rn(v.y - __half2float(h1));
        __half l2 = __float2half_rn(v.z - __half2float(h2));
        __half l3 = __float2half_rn(v.w - __half2float(h3));
        int idx = row * 64 + (((colI >> 3) ^ (row & 7)) << 3) + (colI & 7);
        __half2* ph = reinterpret_cast<__half2*>(ah + idx);
        __half2* pl = reinterpret_cast<__half2*>(al + idx);
        ph[0] = __halves2half2(h0, h1); ph[1] = __halves2half2(h2, h3);
        pl[0] = __halves2half2(l0, l1); pl[1] = __halves2half2(l2, l3);
    }
}

__device__ __forceinline__ void chunk_mainloop(uint32_t sb, int ck, int wm, int wn, int lane,
                                               float (&acc)[4][4][4]) {
    const int aRowL = lane & 15;
    const int aSel  = lane >> 4;
    const int sx    = lane & 7;
    const int bRowL = lane & 7;
    const int bSel  = (lane >> 3) & 1;
    #pragma unroll
    for (int ks = 0; ks < 4; ++ks) {
        uint32_t ah[4][4], al[4][4], bh[4][2], bl[4][2];
        #pragma unroll
        for (int mt = 0; mt < 4; ++mt) {
            int row = wm * 64 + mt * 16 + aRowL;
            uint32_t off = (uint32_t)row * 128 + (uint32_t)(((ks * 2 + aSel) ^ sx) << 4);
            ldsm_x4(ah[mt], sb + SM_A_HI + off);
            ldsm_x4(al[mt], sb + SM_A_LO + off);
        }
        int kg = ck * 4 + ks;
        #pragma unroll
        for (int nt = 0; nt < 4; ++nt) {
            int row = wn * 32 + nt * 8 + bRowL;
            uint32_t off = (uint32_t)row * 256 + (uint32_t)(((kg * 2 + bSel) ^ sx) << 4);
            ldsm_x2(bh[nt], sb + SM_B_HI + off);
            ldsm_x2(bl[nt], sb + SM_B_LO + off);
        }
        #pragma unroll
        for (int mt = 0; mt < 4; ++mt)
            #pragma unroll
            for (int nt = 0; nt < 4; ++nt) {
                mma16816(acc[mt][nt], ah[mt], bh[nt]);
                mma16816(acc[mt][nt], al[mt], bh[nt]);
                mma16816(acc[mt][nt], ah[mt], bl[nt]);
            }
    }
}

// ---------------- GEMM1: agg(f32) @ W1 + bias, BN, ReLU -> mid(f32) ----------
__global__ __launch_bounds__(256, 2)
void gemm1_mma(const float* __restrict__ A,
               const __half* __restrict__ bhi, const __half* __restrict__ blo,
               const float* __restrict__ bias,
               const float* __restrict__ gamma, const float* __restrict__ beta,
               float* __restrict__ out, int M) {
    extern __shared__ __align__(16) char smem[];
    const uint32_t sb = smem_u32(smem);
    const int tid  = threadIdx.x;
    const int wid  = tid >> 5;
    const int lane = tid & 31;
    const int wm   = wid >> 2;
    const int wn   = wid & 3;
    const int rowBase = blockIdx.x * 128;

    copy_b(smem, tid, bhi, blo);

    float acc[4][4][4];
    #pragma unroll
    for (int i = 0; i < 4; ++i)
        #pragma unroll
        for (int j = 0; j < 4; ++j)
            #pragma unroll
            for (int r = 0; r < 4; ++r) acc[i][j][r] = 0.f;

    #pragma unroll
    for (int ck = 0; ck < 2; ++ck) {
        if (ck == 1) __syncthreads();
        load_a_chunk(smem, tid, A, rowBase, ck, M);
        __syncthreads();
        chunk_mainloop(sb, ck, wm, wn, lane, acc);
    }

    const int g8  = lane >> 2;
    const int tig = lane & 3;
    #pragma unroll
    for (int nt = 0; nt < 4; ++nt) {
        int c0 = wn * 32 + nt * 8 + 2 * tig;
        float cb0 = __ldg(bias + c0),      cb1 = __ldg(bias + c0 + 1);
        float cs0 = __ldg(gamma + c0)     * 0.9999950000374997f;
        float cs1 = __ldg(gamma + c0 + 1) * 0.9999950000374997f;
        float ct0 = __ldg(beta + c0),      ct1 = __ldg(beta + c0 + 1);
        #pragma unroll
        for (int mt = 0; mt < 4; ++mt) {
            #pragma unroll
            for (int hf = 0; hf < 2; ++hf) {
                int row = rowBase + wm * 64 + mt * 16 + g8 + hf * 8;
                if (row < M) {
                    float v0 = fmaxf((acc[mt][nt][2 * hf + 0] + cb0) * cs0 + ct0, 0.f);
                    float v1 = fmaxf((acc[mt][nt][2 * hf + 1] + cb1) * cs1 + ct1, 0.f);
                    *reinterpret_cast<float2*>(out + (size_t)row * DH + c0) =
                        make_float2(v0, v1);
                }
            }
        }
    }
}

// ---------------- GEMM2: mid @ W2 + bias, ReLU -> pool (+ fp16 h store) ------
template<bool DO_OUT>
__global__ __launch_bounds__(256, 2)
void gemm2_mma(const float* __restrict__ A,
               const __half* __restrict__ bhi, const __half* __restrict__ blo,
               const float* __restrict__ bias,
               __half* __restrict__ hout,
               const int* __restrict__ batch, int poolOff, int M) {
    extern __shared__ __align__(16) char smem[];
    const uint32_t sb = smem_u32(smem);
    const int tid  = threadIdx.x;
    const int wid  = tid >> 5;
    const int lane = tid & 31;
    const int wm   = wid >> 2;
    const int wn   = wid & 3;
    const int rowBase = blockIdx.x * 128;

    copy_b(smem, tid, bhi, blo);

    float acc[4][4][4];
    #pragma unroll
    for (int i = 0; i < 4; ++i)
        #pragma unroll
        for (int j = 0; j < 4; ++j)
            #pragma unroll
            for (int r = 0; r < 4; ++r) acc[i][j][r] = 0.f;

    #pragma unroll
    for (int ck = 0; ck < 2; ++ck) {
        if (ck == 1) __syncthreads();
        load_a_chunk(smem, tid, A, rowBase, ck, M);
        __syncthreads();
        chunk_mainloop(sb, ck, wm, wn, lane, acc);
    }

    const int g8  = lane >> 2;
    const int tig = lane & 3;
    #pragma unroll
    for (int mt = 0; mt < 4; ++mt) {
        #pragma unroll
        for (int hf = 0; hf < 2; ++hf) {
            int row = rowBase + wm * 64 + mt * 16 + g8 + hf * 8;
            if (row < M) {
                int gI = __ldg(batch + row);
                #pragma unroll
                for (int nt = 0; nt < 4; ++nt) {
                    int c0 = wn * 32 + nt * 8 + 2 * tig;
                    float v0 = fmaxf(acc[mt][nt][2 * hf + 0] + __ldg(bias + c0), 0.f);
                    float v1 = fmaxf(acc[mt][nt][2 * hf + 1] + __ldg(bias + c0 + 1), 0.f);
                    if (DO_OUT)
                        *reinterpret_cast<__half2*>(hout + (size_t)row * DH + c0) =
                            __floats2half2_rn(v0, v1);
                    red_add_v2(g_pool + (size_t)gI * (3 * DH) + poolOff + c0, v0, v1);
                }
            }
        }
    }
}

// ---------------- final MLP ----------------
__global__ void final_kernel(const float* __restrict__ pool,
                             const float* __restrict__ w1, const float* __restrict__ b1,
                             const float* __restrict__ w2, const float* __restrict__ b2,
                             float* __restrict__ out) {
    int g = blockIdx.x;
    int tid = threadIdx.x;
    __shared__ float p[384];
    __shared__ float h[384];
    p[tid] = pool[(size_t)g * 384 + tid];
    __syncthreads();
    float acc = b1[tid];
    #pragma unroll 4
    for (int k = 0; k < 384; ++k) acc += p[k] * w1[(size_t)k * 384 + tid];
    h[tid] = fmaxf(acc, 0.f);
    __syncthreads();
    if (tid < 320) {
        int j = tid >> 5, lane = tid & 31;
        float s = 0.f;
        for (int k = lane; k < 384; k += 32) s += h[k] * w2[(size_t)k * 10 + j];
        #pragma unroll
        for (int o = 16; o > 0; o >>= 1) s += __shfl_down_sync(0xffffffffu, s, o);
        if (lane == 0) out[g * 10 + j] = s + b2[j];
    }
}

// ---------------- launch ----------------
extern "C" void kernel_launch(void* const* d_in, const int* in_sizes, int n_in,
                              void* d_out, int out_size) {
    const float* x     = (const float*)d_in[0];
    const int*   ei    = (const int*)d_in[1];
    const int*   batch = (const int*)d_in[2];
    const int E   = in_sizes[1] / 2;
    const int M   = in_sizes[0] / DH;
    const int* src = ei;
    const int* dst = ei + E;

    float *agg, *mid, *pool;
    __half *xh, *hh, *bhi, *blo;
    int *cnt, *rowptr, *cursor, *col, *bsum;
    cudaGetSymbolAddress((void**)&agg,    g_agg);
    cudaGetSymbolAddress((void**)&mid,    g_mid);
    cudaGetSymbolAddress((void**)&xh,     g_xh);
    cudaGetSymbolAddress((void**)&hh,     g_hh);
    cudaGetSymbolAddress((void**)&pool,   g_pool);
    cudaGetSymbolAddress((void**)&bhi,    g_bhi);
    cudaGetSymbolAddress((void**)&blo,    g_blo);
    cudaGetSymbolAddress((void**)&cnt,    g_cnt);
    cudaGetSymbolAddress((void**)&rowptr, g_rowptr);
    cudaGetSymbolAddress((void**)&cursor, g_cursor);
    cudaGetSymbolAddress((void**)&col,    g_col);
    cudaGetSymbolAddress((void**)&bsum,   g_bsum);

    cudaFuncSetAttribute(gemm1_mma,        cudaFuncAttributeMaxDynamicSharedMemorySize, SM_TOT);
    cudaFuncSetAttribute(gemm2_mma<true>,  cudaFuncAttributeMaxDynamicSharedMemorySize, SM_TOT);
    cudaFuncSetAttribute(gemm2_mma<false>, cudaFuncAttributeMaxDynamicSharedMemorySize, SM_TOT);

    // ---- CSR build ----
    zero_i<<<(M + 255) / 256, 256>>>(cnt, M);
    hist_kernel<<<(E + 255) / 256, 256>>>(dst, cnt, E);
    scan1_kernel<<<NB_SCAN, 1024>>>(cnt, rowptr, bsum, M);
    scan2_kernel<<<1, 128>>>(bsum, NB_SCAN);
    scan3_kernel<<<(M + 255) / 256, 256>>>(rowptr, cursor, bsum, M, E);
    fill_kernel<<<(E + 255) / 256, 256>>>(src, dst, cursor, col, E);

    // ---- prep: weights split/swizzle, x -> fp16, zero pool ----
    prep_b_kernel<<<(6 * 16384 + 255) / 256, 256>>>(
        (const float*)d_in[3],  (const float*)d_in[7],
        (const float*)d_in[9],  (const float*)d_in[13],
        (const float*)d_in[15], (const float*)d_in[19]);
    prep_x_kernel<<<(M * DH / 2 + 255) / 256, 256>>>(x, xh, M * DH / 2);
    {
        int n4 = NGRAPHS * 3 * DH / 4;
        zero_f4<<<(n4 + 255) / 256, 256>>>(pool, n4);
    }

    const __half* gin = xh;
    const int gblocks = (M + 127) / 128;
    const int gatherBlocks = (M * 32 + 255) / 256;

    for (int l = 0; l < 3; ++l) {
        const float* bias1 = (const float*)d_in[3 + 6 * l + 1];
        const float* gamma = (const float*)d_in[3 + 6 * l + 2];
        const float* beta  = (const float*)d_in[3 + 6 * l + 3];
        const float* bias2 = (const float*)d_in[3 + 6 * l + 5];
        const __half* bh1 = bhi + (size_t)(2 * l + 0) * 16384;
        const __half* bl1 = blo + (size_t)(2 * l + 0) * 16384;
        const __half* bh2 = bhi + (size_t)(2 * l + 1) * 16384;
        const __half* bl2 = blo + (size_t)(2 * l + 1) * 16384;

        gather_f16<<<gatherBlocks, 256>>>(gin, rowptr, col, agg, M);
        gemm1_mma<<<gblocks, 256, SM_TOT>>>(
            agg, bh1, bl1, bias1, gamma, beta, mid, M);
        if (l < 2)
            gemm2_mma<true><<<gblocks, 256, SM_TOT>>>(
                mid, bh2, bl2, bias2, hh, batch, l * DH, M);
        else
            gemm2_mma<false><<<gblocks, 256, SM_TOT>>>(
                mid, bh2, bl2, bias2, nullptr, batch, l * DH, M);
        gin = hh;
    }

    final_kernel<<<NGRAPHS, 384>>>(pool,
                                   (const float*)d_in[21], (const float*)d_in[22],
                                   (const float*)d_in[23], (const float*)d_in[24],
                                   (float*)d_out);
}